// round 13
// baseline (speedup 1.0000x reference)
#include <cuda_runtime.h>
#include <cuda_fp16.h>
#include <math.h>

#define NN 50000
#define EE 800000
#define KKER 8
#define NBLK_SCAN ((NN + 255) / 256)   // 196

// ---------------- scratch (static device globals; no allocation) ------------
// xt layout: [row][kblk*32 + c'], half2 = channels (2c', 2c'+1)  = 51.2 MB
__device__ __half2 g_xt_h[(size_t)NN * 256];
__device__ float   g_root[(size_t)NN * 64];   // x @ W_root   12.8 MB
__device__ float   g_agg[(size_t)NN * 64];    // scatter target 12.8 MB
__device__ float   g_sums[128];               // [0:64) sum, [64:128) sumsq
__device__ int     g_is64;
__device__ __half  g_Bh[9 * 4096];            // pre-swizzled B tiles (73.7 KB)
// CSR-by-src structures
__device__ int     g_deg_src[NN];
__device__ int     g_deg_dst[NN];
__device__ int     g_off[NN + 1];
__device__ int     g_cur[NN];
__device__ int     g_part[NBLK_SCAN];
__device__ int     g_partoff[NBLK_SCAN];
__device__ int2    g_rec[EE];                 // {dst, e} per CSR slot   6.4 MB
__device__ float   g_gk[(size_t)EE * 8];      // gauss weights, EDGE order 25.6 MB

__device__ __forceinline__ unsigned h2_as_u32(__half2 h) {
    return *(unsigned*)&h;
}
__device__ __forceinline__ void red_add_v2(float* p, float a, float b) {
    asm volatile("red.global.add.v2.f32 [%0], {%1, %2};"
                 :: "l"(p), "f"(a), "f"(b) : "memory");
}

// ---------------- K_detect ---------------------------------------------------
__global__ void k_detect(const int* __restrict__ eidx_raw) {
    __shared__ int sh[8];
    int acc = 0;
    for (int i = threadIdx.x; i < 2048; i += 256) acc |= eidx_raw[2 * i + 1];
    for (int o = 16; o > 0; o >>= 1) acc |= __shfl_xor_sync(0xffffffffu, acc, o);
    if ((threadIdx.x & 31) == 0) sh[threadIdx.x >> 5] = acc;
    __syncthreads();
    if (threadIdx.x == 0) {
        int a = 0;
        #pragma unroll
        for (int i = 0; i < 8; i++) a |= sh[i];
        g_is64 = (a == 0) ? 1 : 0;
    }
}

// ---------------- K_zero ------------------------------------------------------
__global__ void k_zero() {
    long i = (long)blockIdx.x * blockDim.x + threadIdx.x;
    const long nagg = (long)NN * 64;
    if (i < nagg) g_agg[i] = 0.0f;
    else if (i < nagg + NN) g_deg_src[i - nagg] = 0;
    else if (i < nagg + 2 * NN) g_deg_dst[i - nagg - NN] = 0;
    else if (i < nagg + 2 * NN + 128) g_sums[i - nagg - 2 * NN] = 0.0f;
}

// ---------------- K_count: degree histograms + gauss weights (edge order) ---
__global__ void k_count(const void* __restrict__ eidx,
                        const float* __restrict__ eattr,
                        const float* __restrict__ mu,
                        const float* __restrict__ sigma) {
    int e = blockIdx.x * 256 + threadIdx.x;
    if (e >= EE) return;
    int src, dst;
    if (g_is64) {
        const long long* e64 = (const long long*)eidx;
        src = (int)e64[e]; dst = (int)e64[EE + e];
    } else {
        const int* e32 = (const int*)eidx;
        src = e32[e]; dst = e32[EE + e];
    }
    atomicAdd(&g_deg_src[src], 1);
    atomicAdd(&g_deg_dst[dst], 1);

    float a0 = eattr[(size_t)e * 3 + 0];
    float a1 = eattr[(size_t)e * 3 + 1];
    float a2 = eattr[(size_t)e * 3 + 2];
    float gk[8];
    #pragma unroll
    for (int k = 0; k < 8; k++) {
        float s0 = sigma[k * 3 + 0], s1 = sigma[k * 3 + 1], s2 = sigma[k * 3 + 2];
        float d0 = a0 - mu[k * 3 + 0];
        float d1 = a1 - mu[k * 3 + 1];
        float d2 = a2 - mu[k * 3 + 2];
        float iv0 = -0.5f / (1e-15f + s0 * s0);
        float iv1 = -0.5f / (1e-15f + s1 * s1);
        float iv2 = -0.5f / (1e-15f + s2 * s2);
        gk[k] = __expf(d0 * d0 * iv0 + d1 * d1 * iv1 + d2 * d2 * iv2);
    }
    float4* gdst = (float4*)&g_gk[(size_t)e * 8];     // coalesced (edge order)
    gdst[0] = make_float4(gk[0], gk[1], gk[2], gk[3]);
    gdst[1] = make_float4(gk[4], gk[5], gk[6], gk[7]);
}

// ---------------- 3-phase parallel exclusive scan over g_deg_src -------------
__global__ __launch_bounds__(256) void k_scan_blk() {
    __shared__ int sh[256];
    const int t = threadIdx.x;
    const int i = blockIdx.x * 256 + t;
    int v = (i < NN) ? g_deg_src[i] : 0;
    sh[t] = v;
    __syncthreads();
    #pragma unroll
    for (int off = 1; off < 256; off <<= 1) {
        int add = (t >= off) ? sh[t - off] : 0;
        __syncthreads();
        sh[t] += add;
        __syncthreads();
    }
    if (i < NN) g_off[i] = sh[t] - v;
    if (t == 255) g_part[blockIdx.x] = sh[t];
}

__global__ __launch_bounds__(256) void k_scan_part() {
    __shared__ int sh[256];
    const int t = threadIdx.x;
    int v = (t < NBLK_SCAN) ? g_part[t] : 0;
    sh[t] = v;
    __syncthreads();
    #pragma unroll
    for (int off = 1; off < 256; off <<= 1) {
        int add = (t >= off) ? sh[t - off] : 0;
        __syncthreads();
        sh[t] += add;
        __syncthreads();
    }
    if (t < NBLK_SCAN) g_partoff[t] = sh[t] - v;
}

__global__ __launch_bounds__(256) void k_scan_add() {
    const int i = blockIdx.x * 256 + threadIdx.x;
    if (i < NN) {
        int o = g_off[i] + g_partoff[blockIdx.x];
        g_off[i] = o;
        g_cur[i] = o;
    }
    if (i == 0) g_off[NN] = EE;
}

// ---------------- K_scatter: bucket edges by src (8B records) ---------------
__global__ void k_scatter(const void* __restrict__ eidx) {
    int e = blockIdx.x * 256 + threadIdx.x;
    if (e >= EE) return;
    int src, dst;
    if (g_is64) {
        const long long* e64 = (const long long*)eidx;
        src = (int)e64[e]; dst = (int)e64[EE + e];
    } else {
        const int* e32 = (const int*)eidx;
        src = e32[e]; dst = e32[EE + e];
    }
    int pos = atomicAdd(&g_cur[src], 1);
    g_rec[pos] = make_int2(dst, e);
}

// ---------------- K_prepB: B^T tiles -> fp16, XOR-swizzled ------------------
__global__ void k_prepB(const float* __restrict__ Wg, const float* __restrict__ Wr) {
    int idx = blockIdx.x * 256 + threadIdx.x;
    if (idx >= 9 * 4096) return;
    int kblk = idx >> 12;
    int n = (idx >> 6) & 63;
    int k = idx & 63;
    float v = (kblk < 8) ? Wg[k * 512 + kblk * 64 + n] : Wr[k * 64 + n];
    int swz = n * 64 + (((k >> 3) ^ (n & 7)) << 3) + (k & 7);
    g_Bh[kblk * 4096 + swz] = __float2half_rn(v);
}

// ---------------- tensor-core GEMM: grid (391, 9), one kblk per block --------
__device__ __forceinline__ unsigned smem_u32(const void* p) {
    return (unsigned)__cvta_generic_to_shared(p);
}
__device__ __forceinline__ void mma16816(float d[4], const unsigned a[4],
                                         unsigned b0, unsigned b1) {
    asm volatile(
        "mma.sync.aligned.m16n8k16.row.col.f32.f16.f16.f32 "
        "{%0,%1,%2,%3}, {%4,%5,%6,%7}, {%8,%9}, {%0,%1,%2,%3};\n"
        : "+f"(d[0]), "+f"(d[1]), "+f"(d[2]), "+f"(d[3])
        : "r"(a[0]), "r"(a[1]), "r"(a[2]), "r"(a[3]), "r"(b0), "r"(b1));
}
#define LDSM_X4(r0, r1, r2, r3, addr)                                        \
    asm volatile("ldmatrix.sync.aligned.m8n8.x4.shared.b16 {%0,%1,%2,%3}, [%4];" \
                 : "=r"(r0), "=r"(r1), "=r"(r2), "=r"(r3) : "r"(addr))

__global__ __launch_bounds__(256) void k_gemm_tc(const float* __restrict__ x)
{
    __shared__ __half As[128 * 64];
    __shared__ __half Bs[64 * 64];

    const int row0 = blockIdx.x * 128;
    const int kblk = blockIdx.y;        // 0..8
    const int tid  = threadIdx.x;
    const int warp = tid >> 5;
    const int lane = tid & 31;
    const int g    = lane >> 2;
    const int t2   = (lane & 3) * 2;
    const int wm = warp & 3;
    const int wn = warp >> 2;

    // fill A (XOR swizzled)
    #pragma unroll
    for (int j = 0; j < 4; j++) {
        int cid = tid + j * 256;
        int r = cid >> 3, kc = cid & 7;
        int gr = row0 + r;
        float4 v0 = make_float4(0.f, 0.f, 0.f, 0.f);
        float4 v1 = make_float4(0.f, 0.f, 0.f, 0.f);
        if (gr < NN) {
            v0 = *(const float4*)&x[(size_t)gr * 64 + kc * 8];
            v1 = *(const float4*)&x[(size_t)gr * 64 + kc * 8 + 4];
        }
        uint4 u;
        u.x = h2_as_u32(__floats2half2_rn(v0.x, v0.y));
        u.y = h2_as_u32(__floats2half2_rn(v0.z, v0.w));
        u.z = h2_as_u32(__floats2half2_rn(v1.x, v1.y));
        u.w = h2_as_u32(__floats2half2_rn(v1.z, v1.w));
        *(uint4*)&As[r * 64 + ((kc ^ (r & 7)) << 3)] = u;
    }
    // copy this kblk's pre-swizzled B tile (linear, conflict-free)
    {
        const uint4* bsrc = (const uint4*)g_Bh + (size_t)kblk * 512;
        uint4* bdst = (uint4*)Bs;
        bdst[tid]       = bsrc[tid];
        bdst[tid + 256] = bsrc[tid + 256];
    }
    __syncthreads();

    // A fragments
    unsigned a[2][4][4];
    #pragma unroll
    for (int ms = 0; ms < 2; ms++)
        #pragma unroll
        for (int kk = 0; kk < 4; kk++) {
            int r  = wm * 32 + ms * 16 + (lane & 15);
            int ch = kk * 2 + (lane >> 4);
            unsigned ad = smem_u32(&As[r * 64 + ((ch ^ (r & 7)) << 3)]);
            LDSM_X4(a[ms][kk][0], a[ms][kk][1], a[ms][kk][2], a[ms][kk][3], ad);
        }

    float acc[2][4][4];
    #pragma unroll
    for (int ms = 0; ms < 2; ms++)
        #pragma unroll
        for (int ns = 0; ns < 4; ns++)
            #pragma unroll
            for (int j = 0; j < 4; j++) acc[ms][ns][j] = 0.0f;

    #pragma unroll
    for (int kk = 0; kk < 4; kk++) {
        int ch = kk * 2 + (lane >> 4);
        int n0 = wn * 16 + (lane & 15);
        int n1 = n0 + 32;
        unsigned b0[4], b1[4];
        LDSM_X4(b0[0], b0[1], b0[2], b0[3],
                smem_u32(&Bs[n0 * 64 + ((ch ^ (n0 & 7)) << 3)]));
        LDSM_X4(b1[0], b1[1], b1[2], b1[3],
                smem_u32(&Bs[n1 * 64 + ((ch ^ (n1 & 7)) << 3)]));
        #pragma unroll
        for (int ms = 0; ms < 2; ms++) {
            mma16816(acc[ms][0], a[ms][kk], b0[0], b0[2]);
            mma16816(acc[ms][1], a[ms][kk], b0[1], b0[3]);
            mma16816(acc[ms][2], a[ms][kk], b1[0], b1[2]);
            mma16816(acc[ms][3], a[ms][kk], b1[1], b1[3]);
        }
    }

    if (kblk < 8) {
        // adjacent-channel pairing: h2 = (col, col+1); word c' = col/2
        #pragma unroll
        for (int ms = 0; ms < 2; ms++)
            #pragma unroll
            for (int ns = 0; ns < 4; ns++) {
                int colbase = wn * 16 + (ns & 1) * 8 + (ns >> 1) * 32 + t2;
                int cw = colbase >> 1;
                int rowb = row0 + wm * 32 + ms * 16 + g;
                if (rowb < NN) {
                    __half2 h = __floats2half2_rn(acc[ms][ns][0], acc[ms][ns][1]);
                    g_xt_h[(size_t)rowb * 256 + kblk * 32 + cw] = h;
                }
                int rowb2 = rowb + 8;
                if (rowb2 < NN) {
                    __half2 h = __floats2half2_rn(acc[ms][ns][2], acc[ms][ns][3]);
                    g_xt_h[(size_t)rowb2 * 256 + kblk * 32 + cw] = h;
                }
            }
    } else {
        #pragma unroll
        for (int ms = 0; ms < 2; ms++)
            #pragma unroll
            for (int ns = 0; ns < 4; ns++)
                #pragma unroll
                for (int j = 0; j < 4; j++) {
                    int row = row0 + wm * 32 + ms * 16 + g + ((j >> 1) ? 8 : 0);
                    int c   = wn * 16 + (ns & 1) * 8 + (ns >> 1) * 32 + t2 + (j & 1);
                    if (row < NN) g_root[(size_t)row * 64 + c] = acc[ms][ns][j];
                }
    }
}

// ---------------- K_aggr: one warp per src node; v2 atomics -----------------
__global__ __launch_bounds__(256) void k_aggr()
{
    const int lane = threadIdx.x & 31;
    const int node = ((int)blockIdx.x * 256 + (int)threadIdx.x) >> 5;
    if (node >= NN) return;

    const int beg = g_off[node];
    const int end = g_off[node + 1];
    if (beg == end) return;

    const __half2* xr = g_xt_h + (size_t)node * 256;
    float2 f[8];
    #pragma unroll
    for (int k = 0; k < 8; k++) f[k] = __half22float2(xr[k * 32 + lane]);

    int e = beg;
    for (; e + 1 < end; e += 2) {
        int2 rA = g_rec[e];
        int2 rB = g_rec[e + 1];
        const float4* ga = (const float4*)&g_gk[(size_t)rA.y * 8];
        const float4* gb = (const float4*)&g_gk[(size_t)rB.y * 8];
        float4 gA0 = ga[0], gA1 = ga[1], gB0 = gb[0], gB1 = gb[1];

        float accA0 = 0.f, accA1 = 0.f, accB0 = 0.f, accB1 = 0.f;
        float gAv[8] = {gA0.x, gA0.y, gA0.z, gA0.w, gA1.x, gA1.y, gA1.z, gA1.w};
        float gBv[8] = {gB0.x, gB0.y, gB0.z, gB0.w, gB1.x, gB1.y, gB1.z, gB1.w};
        #pragma unroll
        for (int k = 0; k < 8; k++) {
            accA0 = fmaf(gAv[k], f[k].x, accA0);
            accA1 = fmaf(gAv[k], f[k].y, accA1);
            accB0 = fmaf(gBv[k], f[k].x, accB0);
            accB1 = fmaf(gBv[k], f[k].y, accB1);
        }

        red_add_v2(&g_agg[(size_t)rA.x * 64 + 2 * lane], accA0, accA1);
        red_add_v2(&g_agg[(size_t)rB.x * 64 + 2 * lane], accB0, accB1);
    }
    if (e < end) {
        int2 rA = g_rec[e];
        const float4* ga = (const float4*)&g_gk[(size_t)rA.y * 8];
        float4 gA0 = ga[0], gA1 = ga[1];
        float gAv[8] = {gA0.x, gA0.y, gA0.z, gA0.w, gA1.x, gA1.y, gA1.z, gA1.w};
        float accA0 = 0.f, accA1 = 0.f;
        #pragma unroll
        for (int k = 0; k < 8; k++) {
            accA0 = fmaf(gAv[k], f[k].x, accA0);
            accA1 = fmaf(gAv[k], f[k].y, accA1);
        }
        red_add_v2(&g_agg[(size_t)rA.x * 64 + 2 * lane], accA0, accA1);
    }
}

// ---------------- K_combine ---------------------------------------------------
__global__ __launch_bounds__(256) void k_combine(
    const float* __restrict__ bias, float* __restrict__ out)
{
    const int c = threadIdx.x & 63;
    const int w = threadIdx.x >> 6;
    const float b = bias[c];

    float s = 0.0f, ss = 0.0f;
    for (int n = blockIdx.x * 4 + w; n < NN; n += gridDim.x * 4) {
        float cnt = (float)g_deg_dst[n];
        float inv = 1.0f / fmaxf(cnt, 1.0f);
        float v = g_agg[(size_t)n * 64 + c] * inv + g_root[(size_t)n * 64 + c] + b;
        out[(size_t)n * 64 + c] = v;
        s += v; ss += v * v;
    }

    __shared__ float shs[4][64];
    __shared__ float shq[4][64];
    shs[w][c] = s; shq[w][c] = ss;
    __syncthreads();
    if (threadIdx.x < 64) {
        float S  = shs[0][c] + shs[1][c] + shs[2][c] + shs[3][c];
        float SS = shq[0][c] + shq[1][c] + shq[2][c] + shq[3][c];
        atomicAdd(&g_sums[c], S);
        atomicAdd(&g_sums[64 + c], SS);
    }
}

// ---------------- K_norm (float4) ---------------------------------------------
__global__ __launch_bounds__(256) void k_norm(
    const float* __restrict__ gamma, const float* __restrict__ beta,
    float* __restrict__ out)
{
    long i = (long)blockIdx.x * blockDim.x + threadIdx.x;   // float4 index
    if (i >= (long)NN * 16) return;
    int c4 = (int)(i & 15) * 4;
    const float invN = 1.0f / (float)NN;
    float4 v = *(float4*)&out[i * 4];
    float r[4] = {v.x, v.y, v.z, v.w};
    #pragma unroll
    for (int j = 0; j < 4; j++) {
        int c = c4 + j;
        float mean = g_sums[c] * invN;
        float var  = g_sums[64 + c] * invN - mean * mean;
        float t = (r[j] - mean) * rsqrtf(var + 1e-5f) * gamma[c] + beta[c];
        r[j] = (t > 0.0f) ? t : 0.01f * t;
    }
    *(float4*)&out[i * 4] = make_float4(r[0], r[1], r[2], r[3]);
}

// ---------------- launcher ------------------------------------------------------
extern "C" void kernel_launch(void* const* d_in, const int* in_sizes, int n_in,
                              void* d_out, int out_size)
{
    const float* x      = (const float*)d_in[0];
    const void*  eidx   = d_in[1];
    const float* eattr  = (const float*)d_in[2];
    const float* Wg     = (const float*)d_in[3];
    const float* mu     = (const float*)d_in[4];
    const float* sigma  = (const float*)d_in[5];
    const float* Wr     = (const float*)d_in[6];
    const float* bias   = (const float*)d_in[7];
    const float* gamma  = (const float*)d_in[8];
    const float* beta   = (const float*)d_in[9];
    float* out = (float*)d_out;

    {
        long total = (long)NN * 64 + 2 * NN + 128;
        int blocks = (int)((total + 255) / 256);
        k_zero<<<blocks, 256>>>();
    }
    k_detect<<<1, 256>>>((const int*)eidx);
    k_count<<<(EE + 255) / 256, 256>>>(eidx, eattr, mu, sigma);
    k_scan_blk<<<NBLK_SCAN, 256>>>();
    k_scan_part<<<1, 256>>>();
    k_scan_add<<<NBLK_SCAN, 256>>>();
    k_scatter<<<(EE + 255) / 256, 256>>>(eidx);
    k_prepB<<<144, 256>>>(Wg, Wr);
    {
        dim3 grid((NN + 127) / 128, 9);
        k_gemm_tc<<<grid, 256>>>(x);
    }
    k_aggr<<<(NN * 32 + 255) / 256, 256>>>();
    k_combine<<<512, 256>>>(bias, out);
    {
        int blocks = (int)(((long)NN * 16 + 255) / 256);
        k_norm<<<blocks, 256>>>(gamma, beta, out);
    }
}

// round 14
// speedup vs baseline: 1.1130x; 1.1130x over previous
#include <cuda_runtime.h>
#include <cuda_fp16.h>
#include <math.h>

#define NN 50000
#define EE 800000
#define KKER 8
#define NBLK_SCAN ((NN + 255) / 256)   // 196
#define NBLK_CNT  ((EE + 255) / 256)   // 3125

// ---------------- scratch (static device globals; no allocation) ------------
// xt layout: [row][kblk*32 + c'], half2 = channels (2c', 2c'+1)  = 51.2 MB
__device__ __half2 g_xt_h[(size_t)NN * 256];
__device__ float   g_root[(size_t)NN * 64];   // x @ W_root   12.8 MB
__device__ float   g_agg[(size_t)NN * 64];    // scatter target 12.8 MB
__device__ float   g_sums[128];               // [0:64) sum, [64:128) sumsq
__device__ int     g_is64;
__device__ __half  g_Bh[9 * 4096];            // pre-swizzled B tiles (73.7 KB)
// CSR-by-src structures
__device__ int     g_deg_src[NN];
__device__ int     g_deg_dst[NN];
__device__ int     g_off[NN + 1];
__device__ int     g_cur[NN];
__device__ int     g_part[NBLK_SCAN];
__device__ int     g_partoff[NBLK_SCAN];
__device__ int     g_recdst[EE];              // dst per CSR slot        3.2 MB
__device__ float   g_gk[(size_t)EE * 8];      // gauss weights, CSR order 25.6 MB

__device__ __forceinline__ unsigned h2_as_u32(__half2 h) {
    return *(unsigned*)&h;
}
__device__ __forceinline__ void red_add_v2(float* p, float a, float b) {
    asm volatile("red.global.add.v2.f32 [%0], {%1, %2};"
                 :: "l"(p), "f"(a), "f"(b) : "memory");
}

// ---------------- K_zero (+ dtype sniff in block 0) ---------------------------
__global__ void k_zero(const int* __restrict__ eidx_raw) {
    long i = (long)blockIdx.x * blockDim.x + threadIdx.x;
    const long nagg = (long)NN * 64;
    if (i < nagg) g_agg[i] = 0.0f;
    else if (i < nagg + NN) g_deg_src[i - nagg] = 0;
    else if (i < nagg + 2 * NN) g_deg_dst[i - nagg - NN] = 0;
    else if (i < nagg + 2 * NN + 128) g_sums[i - nagg - 2 * NN] = 0.0f;

    if (blockIdx.x == 0) {
        __shared__ int sh[8];
        int acc = 0;
        for (int j = threadIdx.x; j < 2048; j += 256) acc |= eidx_raw[2 * j + 1];
        for (int o = 16; o > 0; o >>= 1) acc |= __shfl_xor_sync(0xffffffffu, acc, o);
        if ((threadIdx.x & 31) == 0) sh[threadIdx.x >> 5] = acc;
        __syncthreads();
        if (threadIdx.x == 0) {
            int a = 0;
            #pragma unroll
            for (int j = 0; j < 8; j++) a |= sh[j];
            g_is64 = (a == 0) ? 1 : 0;
        }
    }
}

// ---------------- K_count: degree hists + gauss (CSR order via scatter later)
// blocks [0, NBLK_CNT): edge counting + per-edge gauss precompute (edge order
// buffer reused CSR-ordered later? NO — gk written CSR-ordered in k_scatter as
// in R12). Here blocks >= NBLK_CNT handle prepB.
__global__ void k_count(const void* __restrict__ eidx,
                        const float* __restrict__ Wg,
                        const float* __restrict__ Wr) {
    int b = blockIdx.x;
    if (b >= NBLK_CNT) {
        // ---- prepB part: B^T tiles -> fp16, XOR-swizzled
        int idx = (b - NBLK_CNT) * 256 + threadIdx.x;
        if (idx >= 9 * 4096) return;
        int kblk = idx >> 12;
        int n = (idx >> 6) & 63;
        int k = idx & 63;
        float v = (kblk < 8) ? Wg[k * 512 + kblk * 64 + n] : Wr[k * 64 + n];
        int swz = n * 64 + (((k >> 3) ^ (n & 7)) << 3) + (k & 7);
        g_Bh[kblk * 4096 + swz] = __float2half_rn(v);
        return;
    }
    int e = b * 256 + threadIdx.x;
    if (e >= EE) return;
    int src, dst;
    if (g_is64) {
        const long long* e64 = (const long long*)eidx;
        src = (int)e64[e]; dst = (int)e64[EE + e];
    } else {
        const int* e32 = (const int*)eidx;
        src = e32[e]; dst = e32[EE + e];
    }
    atomicAdd(&g_deg_src[src], 1);
    atomicAdd(&g_deg_dst[dst], 1);
}

// ---------------- warp-shuffle scans ------------------------------------------
__global__ __launch_bounds__(256) void k_scan_blk() {
    __shared__ int wsum[8];
    const int t = threadIdx.x;
    const int i = blockIdx.x * 256 + t;
    const int lane = t & 31, w = t >> 5;
    int v = (i < NN) ? g_deg_src[i] : 0;
    int s = v;
    #pragma unroll
    for (int o = 1; o < 32; o <<= 1) {
        int n = __shfl_up_sync(0xffffffffu, s, o);
        if (lane >= o) s += n;
    }
    if (lane == 31) wsum[w] = s;
    __syncthreads();
    if (w == 0) {
        int ws = (lane < 8) ? wsum[lane] : 0;
        #pragma unroll
        for (int o = 1; o < 8; o <<= 1) {
            int n = __shfl_up_sync(0xffffffffu, ws, o);
            if (lane >= o) ws += n;
        }
        if (lane < 8) wsum[lane] = ws;
    }
    __syncthreads();
    int off = (w > 0) ? wsum[w - 1] : 0;
    if (i < NN) g_off[i] = off + s - v;       // exclusive
    if (t == 255) g_part[blockIdx.x] = wsum[7];
}

__global__ __launch_bounds__(256) void k_scan_part() {
    __shared__ int wsum[8];
    const int t = threadIdx.x;
    const int lane = t & 31, w = t >> 5;
    int v = (t < NBLK_SCAN) ? g_part[t] : 0;
    int s = v;
    #pragma unroll
    for (int o = 1; o < 32; o <<= 1) {
        int n = __shfl_up_sync(0xffffffffu, s, o);
        if (lane >= o) s += n;
    }
    if (lane == 31) wsum[w] = s;
    __syncthreads();
    if (w == 0) {
        int ws = (lane < 8) ? wsum[lane] : 0;
        #pragma unroll
        for (int o = 1; o < 8; o <<= 1) {
            int n = __shfl_up_sync(0xffffffffu, ws, o);
            if (lane >= o) ws += n;
        }
        if (lane < 8) wsum[lane] = ws;
    }
    __syncthreads();
    int off = (w > 0) ? wsum[w - 1] : 0;
    if (t < NBLK_SCAN) g_partoff[t] = off + s - v;
}

__global__ __launch_bounds__(256) void k_scan_add() {
    const int i = blockIdx.x * 256 + threadIdx.x;
    if (i < NN) {
        int o = g_off[i] + g_partoff[blockIdx.x];
        g_off[i] = o;
        g_cur[i] = o;
    }
    if (i == 0) g_off[NN] = EE;
}

// ---------------- K_scatter: bucket by src; gauss in CSR order (R12) --------
__global__ void k_scatter(const void* __restrict__ eidx,
                          const float* __restrict__ eattr,
                          const float* __restrict__ mu,
                          const float* __restrict__ sigma) {
    int e = blockIdx.x * 256 + threadIdx.x;
    if (e >= EE) return;
    int src, dst;
    if (g_is64) {
        const long long* e64 = (const long long*)eidx;
        src = (int)e64[e]; dst = (int)e64[EE + e];
    } else {
        const int* e32 = (const int*)eidx;
        src = e32[e]; dst = e32[EE + e];
    }
    float a0 = eattr[(size_t)e * 3 + 0];
    float a1 = eattr[(size_t)e * 3 + 1];
    float a2 = eattr[(size_t)e * 3 + 2];

    int pos = atomicAdd(&g_cur[src], 1);
    g_recdst[pos] = dst;

    float gk[8];
    #pragma unroll
    for (int k = 0; k < 8; k++) {
        float s0 = sigma[k * 3 + 0], s1 = sigma[k * 3 + 1], s2 = sigma[k * 3 + 2];
        float d0 = a0 - mu[k * 3 + 0];
        float d1 = a1 - mu[k * 3 + 1];
        float d2 = a2 - mu[k * 3 + 2];
        float iv0 = -0.5f / (1e-15f + s0 * s0);
        float iv1 = -0.5f / (1e-15f + s1 * s1);
        float iv2 = -0.5f / (1e-15f + s2 * s2);
        gk[k] = __expf(d0 * d0 * iv0 + d1 * d1 * iv1 + d2 * d2 * iv2);
    }
    float4* gdst = (float4*)&g_gk[(size_t)pos * 8];
    gdst[0] = make_float4(gk[0], gk[1], gk[2], gk[3]);
    gdst[1] = make_float4(gk[4], gk[5], gk[6], gk[7]);
}

// ---------------- tensor-core GEMM (R12: single pass, 9-kblk loop) -----------
__device__ __forceinline__ unsigned smem_u32(const void* p) {
    return (unsigned)__cvta_generic_to_shared(p);
}
__device__ __forceinline__ void mma16816(float d[4], const unsigned a[4],
                                         unsigned b0, unsigned b1) {
    asm volatile(
        "mma.sync.aligned.m16n8k16.row.col.f32.f16.f16.f32 "
        "{%0,%1,%2,%3}, {%4,%5,%6,%7}, {%8,%9}, {%0,%1,%2,%3};\n"
        : "+f"(d[0]), "+f"(d[1]), "+f"(d[2]), "+f"(d[3])
        : "r"(a[0]), "r"(a[1]), "r"(a[2]), "r"(a[3]), "r"(b0), "r"(b1));
}
#define LDSM_X4(r0, r1, r2, r3, addr)                                        \
    asm volatile("ldmatrix.sync.aligned.m8n8.x4.shared.b16 {%0,%1,%2,%3}, [%4];" \
                 : "=r"(r0), "=r"(r1), "=r"(r2), "=r"(r3) : "r"(addr))

__global__ __launch_bounds__(256) void k_gemm_tc(const float* __restrict__ x)
{
    __shared__ __half As[128 * 64];
    __shared__ __half Bs[64 * 64];

    const int row0 = blockIdx.x * 128;
    const int tid  = threadIdx.x;
    const int warp = tid >> 5;
    const int lane = tid & 31;
    const int g    = lane >> 2;
    const int t2   = (lane & 3) * 2;
    const int wm = warp & 3;
    const int wn = warp >> 2;

    #pragma unroll
    for (int j = 0; j < 4; j++) {
        int cid = tid + j * 256;
        int r = cid >> 3, kc = cid & 7;
        int gr = row0 + r;
        float4 v0 = make_float4(0.f, 0.f, 0.f, 0.f);
        float4 v1 = make_float4(0.f, 0.f, 0.f, 0.f);
        if (gr < NN) {
            v0 = *(const float4*)&x[(size_t)gr * 64 + kc * 8];
            v1 = *(const float4*)&x[(size_t)gr * 64 + kc * 8 + 4];
        }
        uint4 u;
        u.x = h2_as_u32(__floats2half2_rn(v0.x, v0.y));
        u.y = h2_as_u32(__floats2half2_rn(v0.z, v0.w));
        u.z = h2_as_u32(__floats2half2_rn(v1.x, v1.y));
        u.w = h2_as_u32(__floats2half2_rn(v1.z, v1.w));
        *(uint4*)&As[r * 64 + ((kc ^ (r & 7)) << 3)] = u;
    }
    __syncthreads();

    unsigned a[2][4][4];
    #pragma unroll
    for (int ms = 0; ms < 2; ms++)
        #pragma unroll
        for (int kk = 0; kk < 4; kk++) {
            int r  = wm * 32 + ms * 16 + (lane & 15);
            int ch = kk * 2 + (lane >> 4);
            unsigned ad = smem_u32(&As[r * 64 + ((ch ^ (r & 7)) << 3)]);
            LDSM_X4(a[ms][kk][0], a[ms][kk][1], a[ms][kk][2], a[ms][kk][3], ad);
        }

    const uint4* bsrc = (const uint4*)g_Bh;
    uint4* bdst = (uint4*)Bs;

    for (int kblk = 0; kblk < 9; kblk++) {
        __syncthreads();
        bdst[tid]       = bsrc[kblk * 512 + tid];
        bdst[tid + 256] = bsrc[kblk * 512 + tid + 256];
        __syncthreads();

        float acc[2][4][4];
        #pragma unroll
        for (int ms = 0; ms < 2; ms++)
            #pragma unroll
            for (int ns = 0; ns < 4; ns++)
                #pragma unroll
                for (int j = 0; j < 4; j++) acc[ms][ns][j] = 0.0f;

        #pragma unroll
        for (int kk = 0; kk < 4; kk++) {
            int ch = kk * 2 + (lane >> 4);
            int n0 = wn * 16 + (lane & 15);
            int n1 = n0 + 32;
            unsigned b0[4], b1[4];
            LDSM_X4(b0[0], b0[1], b0[2], b0[3],
                    smem_u32(&Bs[n0 * 64 + ((ch ^ (n0 & 7)) << 3)]));
            LDSM_X4(b1[0], b1[1], b1[2], b1[3],
                    smem_u32(&Bs[n1 * 64 + ((ch ^ (n1 & 7)) << 3)]));
            #pragma unroll
            for (int ms = 0; ms < 2; ms++) {
                mma16816(acc[ms][0], a[ms][kk], b0[0], b0[2]);
                mma16816(acc[ms][1], a[ms][kk], b0[1], b0[3]);
                mma16816(acc[ms][2], a[ms][kk], b1[0], b1[2]);
                mma16816(acc[ms][3], a[ms][kk], b1[1], b1[3]);
            }
        }

        if (kblk < 8) {
            // adjacent-channel pairing: h2 = (col, col+1); word c' = col/2
            #pragma unroll
            for (int ms = 0; ms < 2; ms++)
                #pragma unroll
                for (int ns = 0; ns < 4; ns++) {
                    int colbase = wn * 16 + (ns & 1) * 8 + (ns >> 1) * 32 + t2;
                    int cw = colbase >> 1;
                    int rowb = row0 + wm * 32 + ms * 16 + g;
                    if (rowb < NN) {
                        __half2 h = __floats2half2_rn(acc[ms][ns][0], acc[ms][ns][1]);
                        g_xt_h[(size_t)rowb * 256 + kblk * 32 + cw] = h;
                    }
                    int rowb2 = rowb + 8;
                    if (rowb2 < NN) {
                        __half2 h = __floats2half2_rn(acc[ms][ns][2], acc[ms][ns][3]);
                        g_xt_h[(size_t)rowb2 * 256 + kblk * 32 + cw] = h;
                    }
                }
        } else {
            #pragma unroll
            for (int ms = 0; ms < 2; ms++)
                #pragma unroll
                for (int ns = 0; ns < 4; ns++)
                    #pragma unroll
                    for (int j = 0; j < 4; j++) {
                        int row = row0 + wm * 32 + ms * 16 + g + ((j >> 1) ? 8 : 0);
                        int c   = wn * 16 + (ns & 1) * 8 + (ns >> 1) * 32 + t2 + (j & 1);
                        if (row < NN) g_root[(size_t)row * 64 + c] = acc[ms][ns][j];
                    }
        }
    }
}

// ---------------- K_aggr: one warp per src node; v2 atomics (R12) -----------
__global__ __launch_bounds__(256) void k_aggr()
{
    const int lane = threadIdx.x & 31;
    const int node = ((int)blockIdx.x * 256 + (int)threadIdx.x) >> 5;
    if (node >= NN) return;

    const int beg = g_off[node];
    const int end = g_off[node + 1];
    if (beg == end) return;

    const __half2* xr = g_xt_h + (size_t)node * 256;
    float2 f[8];
    #pragma unroll
    for (int k = 0; k < 8; k++) f[k] = __half22float2(xr[k * 32 + lane]);

    int e = beg;
    for (; e + 1 < end; e += 2) {
        int dstA = g_recdst[e];
        int dstB = g_recdst[e + 1];
        const float4* ga = (const float4*)&g_gk[(size_t)e * 8];
        float4 gA0 = ga[0], gA1 = ga[1], gB0 = ga[2], gB1 = ga[3];

        float accA0 = 0.f, accA1 = 0.f, accB0 = 0.f, accB1 = 0.f;
        float gAv[8] = {gA0.x, gA0.y, gA0.z, gA0.w, gA1.x, gA1.y, gA1.z, gA1.w};
        float gBv[8] = {gB0.x, gB0.y, gB0.z, gB0.w, gB1.x, gB1.y, gB1.z, gB1.w};
        #pragma unroll
        for (int k = 0; k < 8; k++) {
            accA0 = fmaf(gAv[k], f[k].x, accA0);
            accA1 = fmaf(gAv[k], f[k].y, accA1);
            accB0 = fmaf(gBv[k], f[k].x, accB0);
            accB1 = fmaf(gBv[k], f[k].y, accB1);
        }

        red_add_v2(&g_agg[(size_t)dstA * 64 + 2 * lane], accA0, accA1);
        red_add_v2(&g_agg[(size_t)dstB * 64 + 2 * lane], accB0, accB1);
    }
    if (e < end) {
        int dstA = g_recdst[e];
        const float4* ga = (const float4*)&g_gk[(size_t)e * 8];
        float4 gA0 = ga[0], gA1 = ga[1];
        float gAv[8] = {gA0.x, gA0.y, gA0.z, gA0.w, gA1.x, gA1.y, gA1.z, gA1.w};
        float accA0 = 0.f, accA1 = 0.f;
        #pragma unroll
        for (int k = 0; k < 8; k++) {
            accA0 = fmaf(gAv[k], f[k].x, accA0);
            accA1 = fmaf(gAv[k], f[k].y, accA1);
        }
        red_add_v2(&g_agg[(size_t)dstA * 64 + 2 * lane], accA0, accA1);
    }
}

// ---------------- K_combine ---------------------------------------------------
__global__ __launch_bounds__(256) void k_combine(
    const float* __restrict__ bias, float* __restrict__ out)
{
    const int c = threadIdx.x & 63;
    const int w = threadIdx.x >> 6;
    const float b = bias[c];

    float s = 0.0f, ss = 0.0f;
    for (int n = blockIdx.x * 4 + w; n < NN; n += gridDim.x * 4) {
        float cnt = (float)g_deg_dst[n];
        float inv = 1.0f / fmaxf(cnt, 1.0f);
        float v = g_agg[(size_t)n * 64 + c] * inv + g_root[(size_t)n * 64 + c] + b;
        out[(size_t)n * 64 + c] = v;
        s += v; ss += v * v;
    }

    __shared__ float shs[4][64];
    __shared__ float shq[4][64];
    shs[w][c] = s; shq[w][c] = ss;
    __syncthreads();
    if (threadIdx.x < 64) {
        float S  = shs[0][c] + shs[1][c] + shs[2][c] + shs[3][c];
        float SS = shq[0][c] + shq[1][c] + shq[2][c] + shq[3][c];
        atomicAdd(&g_sums[c], S);
        atomicAdd(&g_sums[64 + c], SS);
    }
}

// ---------------- K_norm (float4) ---------------------------------------------
__global__ __launch_bounds__(256) void k_norm(
    const float* __restrict__ gamma, const float* __restrict__ beta,
    float* __restrict__ out)
{
    long i = (long)blockIdx.x * blockDim.x + threadIdx.x;   // float4 index
    if (i >= (long)NN * 16) return;
    int c4 = (int)(i & 15) * 4;
    const float invN = 1.0f / (float)NN;
    float4 v = *(float4*)&out[i * 4];
    float r[4] = {v.x, v.y, v.z, v.w};
    #pragma unroll
    for (int j = 0; j < 4; j++) {
        int c = c4 + j;
        float mean = g_sums[c] * invN;
        float var  = g_sums[64 + c] * invN - mean * mean;
        float t = (r[j] - mean) * rsqrtf(var + 1e-5f) * gamma[c] + beta[c];
        r[j] = (t > 0.0f) ? t : 0.01f * t;
    }
    *(float4*)&out[i * 4] = make_float4(r[0], r[1], r[2], r[3]);
}

// ---------------- launcher ------------------------------------------------------
extern "C" void kernel_launch(void* const* d_in, const int* in_sizes, int n_in,
                              void* d_out, int out_size)
{
    const float* x      = (const float*)d_in[0];
    const void*  eidx   = d_in[1];
    const float* eattr  = (const float*)d_in[2];
    const float* Wg     = (const float*)d_in[3];
    const float* mu     = (const float*)d_in[4];
    const float* sigma  = (const float*)d_in[5];
    const float* Wr     = (const float*)d_in[6];
    const float* bias   = (const float*)d_in[7];
    const float* gamma  = (const float*)d_in[8];
    const float* beta   = (const float*)d_in[9];
    float* out = (float*)d_out;

    {
        long total = (long)NN * 64 + 2 * NN + 128;
        int blocks = (int)((total + 255) / 256);
        k_zero<<<blocks, 256>>>((const int*)eidx);
    }
    k_count<<<NBLK_CNT + 144, 256>>>(eidx, Wg, Wr);
    k_scan_blk<<<NBLK_SCAN, 256>>>();
    k_scan_part<<<1, 256>>>();
    k_scan_add<<<NBLK_SCAN, 256>>>();
    k_scatter<<<(EE + 255) / 256, 256>>>(eidx, eattr, mu, sigma);
    k_gemm_tc<<<(NN + 127) / 128, 256>>>(x);
    k_aggr<<<(NN * 32 + 255) / 256, 256>>>();
    k_combine<<<512, 256>>>(bias, out);
    {
        int blocks = (int)(((long)NN * 16 + 255) / 256);
        k_norm<<<blocks, 256>>>(gamma, beta, out);
    }
}

// round 15
// speedup vs baseline: 1.2164x; 1.0929x over previous
#include <cuda_runtime.h>
#include <cuda_fp16.h>
#include <math.h>

#define NN 50000
#define EE 800000
#define KKER 8
#define NBLK_SCAN ((NN + 255) / 256)   // 196
#define NBLK_CNT  ((EE + 255) / 256)   // 3125

// ---------------- scratch (static device globals; no allocation) ------------
// xt layout: [row][kblk*32 + c'], half2 = channels (2c', 2c'+1)  = 51.2 MB
__device__ __half2 g_xt_h[(size_t)NN * 256];
__device__ float   g_root[(size_t)NN * 64];   // x @ W_root   12.8 MB
__device__ float   g_agg[(size_t)NN * 64];    // scatter target 12.8 MB
__device__ float   g_sums[128];               // [0:64) sum, [64:128) sumsq
__device__ int     g_is64;
__device__ __half  g_Bh[9 * 4096];            // pre-swizzled B tiles (73.7 KB)
// CSR-by-src structures
__device__ int     g_deg_src[NN];
__device__ int     g_deg_dst[NN];
__device__ int     g_off[NN + 1];
__device__ int     g_cur[NN];
__device__ int     g_part[NBLK_SCAN];
__device__ int     g_partoff[NBLK_SCAN];
__device__ int     g_recdst[EE];              // dst per CSR slot        3.2 MB
__device__ float   g_gk[(size_t)EE * 8];      // gauss weights, CSR order 25.6 MB

__device__ __forceinline__ unsigned h2_as_u32(__half2 h) {
    return *(unsigned*)&h;
}
__device__ __forceinline__ void red_add_v2(float* p, float a, float b) {
    asm volatile("red.global.add.v2.f32 [%0], {%1, %2};"
                 :: "l"(p), "f"(a), "f"(b) : "memory");
}

// ---------------- K_zero (+ dtype sniff in block 0) ---------------------------
__global__ void k_zero(const int* __restrict__ eidx_raw) {
    long i = (long)blockIdx.x * blockDim.x + threadIdx.x;
    const long nagg = (long)NN * 64;
    if (i < nagg) g_agg[i] = 0.0f;
    else if (i < nagg + NN) g_deg_src[i - nagg] = 0;
    else if (i < nagg + 2 * NN) g_deg_dst[i - nagg - NN] = 0;
    else if (i < nagg + 2 * NN + 128) g_sums[i - nagg - 2 * NN] = 0.0f;

    if (blockIdx.x == 0) {
        __shared__ int sh[8];
        int acc = 0;
        for (int j = threadIdx.x; j < 2048; j += 256) acc |= eidx_raw[2 * j + 1];
        for (int o = 16; o > 0; o >>= 1) acc |= __shfl_xor_sync(0xffffffffu, acc, o);
        if ((threadIdx.x & 31) == 0) sh[threadIdx.x >> 5] = acc;
        __syncthreads();
        if (threadIdx.x == 0) {
            int a = 0;
            #pragma unroll
            for (int j = 0; j < 8; j++) a |= sh[j];
            g_is64 = (a == 0) ? 1 : 0;
        }
    }
}

// ---------------- K_count: degree histograms --------------------------------
__global__ void k_count(const void* __restrict__ eidx) {
    int e = blockIdx.x * 256 + threadIdx.x;
    if (e >= EE) return;
    int src, dst;
    if (g_is64) {
        const long long* e64 = (const long long*)eidx;
        src = (int)e64[e]; dst = (int)e64[EE + e];
    } else {
        const int* e32 = (const int*)eidx;
        src = e32[e]; dst = e32[EE + e];
    }
    atomicAdd(&g_deg_src[src], 1);
    atomicAdd(&g_deg_dst[dst], 1);
}

// ---------------- warp-shuffle scans ------------------------------------------
__global__ __launch_bounds__(256) void k_scan_blk() {
    __shared__ int wsum[8];
    const int t = threadIdx.x;
    const int i = blockIdx.x * 256 + t;
    const int lane = t & 31, w = t >> 5;
    int v = (i < NN) ? g_deg_src[i] : 0;
    int s = v;
    #pragma unroll
    for (int o = 1; o < 32; o <<= 1) {
        int n = __shfl_up_sync(0xffffffffu, s, o);
        if (lane >= o) s += n;
    }
    if (lane == 31) wsum[w] = s;
    __syncthreads();
    if (w == 0) {
        int ws = (lane < 8) ? wsum[lane] : 0;
        #pragma unroll
        for (int o = 1; o < 8; o <<= 1) {
            int n = __shfl_up_sync(0xffffffffu, ws, o);
            if (lane >= o) ws += n;
        }
        if (lane < 8) wsum[lane] = ws;
    }
    __syncthreads();
    int off = (w > 0) ? wsum[w - 1] : 0;
    if (i < NN) g_off[i] = off + s - v;       // exclusive
    if (t == 255) g_part[blockIdx.x] = wsum[7];
}

__global__ __launch_bounds__(256) void k_scan_part() {
    __shared__ int wsum[8];
    const int t = threadIdx.x;
    const int lane = t & 31, w = t >> 5;
    int v = (t < NBLK_SCAN) ? g_part[t] : 0;
    int s = v;
    #pragma unroll
    for (int o = 1; o < 32; o <<= 1) {
        int n = __shfl_up_sync(0xffffffffu, s, o);
        if (lane >= o) s += n;
    }
    if (lane == 31) wsum[w] = s;
    __syncthreads();
    if (w == 0) {
        int ws = (lane < 8) ? wsum[lane] : 0;
        #pragma unroll
        for (int o = 1; o < 8; o <<= 1) {
            int n = __shfl_up_sync(0xffffffffu, ws, o);
            if (lane >= o) ws += n;
        }
        if (lane < 8) wsum[lane] = ws;
    }
    __syncthreads();
    int off = (w > 0) ? wsum[w - 1] : 0;
    if (t < NBLK_SCAN) g_partoff[t] = off + s - v;
}

__global__ __launch_bounds__(256) void k_scan_add() {
    const int i = blockIdx.x * 256 + threadIdx.x;
    if (i < NN) {
        int o = g_off[i] + g_partoff[blockIdx.x];
        g_off[i] = o;
        g_cur[i] = o;
    }
    if (i == 0) g_off[NN] = EE;
}

// ---------------- K_scatter: bucket by src; gauss in CSR order --------------
__global__ void k_scatter(const void* __restrict__ eidx,
                          const float* __restrict__ eattr,
                          const float* __restrict__ mu,
                          const float* __restrict__ sigma) {
    int e = blockIdx.x * 256 + threadIdx.x;
    if (e >= EE) return;
    int src, dst;
    if (g_is64) {
        const long long* e64 = (const long long*)eidx;
        src = (int)e64[e]; dst = (int)e64[EE + e];
    } else {
        const int* e32 = (const int*)eidx;
        src = e32[e]; dst = e32[EE + e];
    }
    float a0 = eattr[(size_t)e * 3 + 0];
    float a1 = eattr[(size_t)e * 3 + 1];
    float a2 = eattr[(size_t)e * 3 + 2];

    int pos = atomicAdd(&g_cur[src], 1);
    g_recdst[pos] = dst;

    float gk[8];
    #pragma unroll
    for (int k = 0; k < 8; k++) {
        float s0 = sigma[k * 3 + 0], s1 = sigma[k * 3 + 1], s2 = sigma[k * 3 + 2];
        float d0 = a0 - mu[k * 3 + 0];
        float d1 = a1 - mu[k * 3 + 1];
        float d2 = a2 - mu[k * 3 + 2];
        float iv0 = -0.5f / (1e-15f + s0 * s0);
        float iv1 = -0.5f / (1e-15f + s1 * s1);
        float iv2 = -0.5f / (1e-15f + s2 * s2);
        gk[k] = __expf(d0 * d0 * iv0 + d1 * d1 * iv1 + d2 * d2 * iv2);
    }
    float4* gdst = (float4*)&g_gk[(size_t)pos * 8];
    gdst[0] = make_float4(gk[0], gk[1], gk[2], gk[3]);
    gdst[1] = make_float4(gk[4], gk[5], gk[6], gk[7]);
}

// ---------------- K_prepB: B^T tiles -> fp16, XOR-swizzled ------------------
__global__ void k_prepB(const float* __restrict__ Wg, const float* __restrict__ Wr) {
    int idx = blockIdx.x * 256 + threadIdx.x;
    if (idx >= 9 * 4096) return;
    int kblk = idx >> 12;
    int n = (idx >> 6) & 63;
    int k = idx & 63;
    float v = (kblk < 8) ? Wg[k * 512 + kblk * 64 + n] : Wr[k * 64 + n];
    int swz = n * 64 + (((k >> 3) ^ (n & 7)) << 3) + (k & 7);
    g_Bh[kblk * 4096 + swz] = __float2half_rn(v);
}

// ---------------- tensor-core GEMM (single pass, 9-kblk loop) ----------------
__device__ __forceinline__ unsigned smem_u32(const void* p) {
    return (unsigned)__cvta_generic_to_shared(p);
}
__device__ __forceinline__ void mma16816(float d[4], const unsigned a[4],
                                         unsigned b0, unsigned b1) {
    asm volatile(
        "mma.sync.aligned.m16n8k16.row.col.f32.f16.f16.f32 "
        "{%0,%1,%2,%3}, {%4,%5,%6,%7}, {%8,%9}, {%0,%1,%2,%3};\n"
        : "+f"(d[0]), "+f"(d[1]), "+f"(d[2]), "+f"(d[3])
        : "r"(a[0]), "r"(a[1]), "r"(a[2]), "r"(a[3]), "r"(b0), "r"(b1));
}
#define LDSM_X4(r0, r1, r2, r3, addr)                                        \
    asm volatile("ldmatrix.sync.aligned.m8n8.x4.shared.b16 {%0,%1,%2,%3}, [%4];" \
                 : "=r"(r0), "=r"(r1), "=r"(r2), "=r"(r3) : "r"(addr))

__global__ __launch_bounds__(256) void k_gemm_tc(const float* __restrict__ x)
{
    __shared__ __half As[128 * 64];
    __shared__ __half Bs[64 * 64];

    const int row0 = blockIdx.x * 128;
    const int tid  = threadIdx.x;
    const int warp = tid >> 5;
    const int lane = tid & 31;
    const int g    = lane >> 2;
    const int t2   = (lane & 3) * 2;
    const int wm = warp & 3;
    const int wn = warp >> 2;

    #pragma unroll
    for (int j = 0; j < 4; j++) {
        int cid = tid + j * 256;
        int r = cid >> 3, kc = cid & 7;
        int gr = row0 + r;
        float4 v0 = make_float4(0.f, 0.f, 0.f, 0.f);
        float4 v1 = make_float4(0.f, 0.f, 0.f, 0.f);
        if (gr < NN) {
            v0 = *(const float4*)&x[(size_t)gr * 64 + kc * 8];
            v1 = *(const float4*)&x[(size_t)gr * 64 + kc * 8 + 4];
        }
        uint4 u;
        u.x = h2_as_u32(__floats2half2_rn(v0.x, v0.y));
        u.y = h2_as_u32(__floats2half2_rn(v0.z, v0.w));
        u.z = h2_as_u32(__floats2half2_rn(v1.x, v1.y));
        u.w = h2_as_u32(__floats2half2_rn(v1.z, v1.w));
        *(uint4*)&As[r * 64 + ((kc ^ (r & 7)) << 3)] = u;
    }
    __syncthreads();

    unsigned a[2][4][4];
    #pragma unroll
    for (int ms = 0; ms < 2; ms++)
        #pragma unroll
        for (int kk = 0; kk < 4; kk++) {
            int r  = wm * 32 + ms * 16 + (lane & 15);
            int ch = kk * 2 + (lane >> 4);
            unsigned ad = smem_u32(&As[r * 64 + ((ch ^ (r & 7)) << 3)]);
            LDSM_X4(a[ms][kk][0], a[ms][kk][1], a[ms][kk][2], a[ms][kk][3], ad);
        }

    const uint4* bsrc = (const uint4*)g_Bh;
    uint4* bdst = (uint4*)Bs;

    for (int kblk = 0; kblk < 9; kblk++) {
        __syncthreads();
        bdst[tid]       = bsrc[kblk * 512 + tid];
        bdst[tid + 256] = bsrc[kblk * 512 + tid + 256];
        __syncthreads();

        float acc[2][4][4];
        #pragma unroll
        for (int ms = 0; ms < 2; ms++)
            #pragma unroll
            for (int ns = 0; ns < 4; ns++)
                #pragma unroll
                for (int j = 0; j < 4; j++) acc[ms][ns][j] = 0.0f;

        #pragma unroll
        for (int kk = 0; kk < 4; kk++) {
            int ch = kk * 2 + (lane >> 4);
            int n0 = wn * 16 + (lane & 15);
            int n1 = n0 + 32;
            unsigned b0[4], b1[4];
            LDSM_X4(b0[0], b0[1], b0[2], b0[3],
                    smem_u32(&Bs[n0 * 64 + ((ch ^ (n0 & 7)) << 3)]));
            LDSM_X4(b1[0], b1[1], b1[2], b1[3],
                    smem_u32(&Bs[n1 * 64 + ((ch ^ (n1 & 7)) << 3)]));
            #pragma unroll
            for (int ms = 0; ms < 2; ms++) {
                mma16816(acc[ms][0], a[ms][kk], b0[0], b0[2]);
                mma16816(acc[ms][1], a[ms][kk], b0[1], b0[3]);
                mma16816(acc[ms][2], a[ms][kk], b1[0], b1[2]);
                mma16816(acc[ms][3], a[ms][kk], b1[1], b1[3]);
            }
        }

        if (kblk < 8) {
            // adjacent-channel pairing: h2 = (col, col+1); word c' = col/2
            #pragma unroll
            for (int ms = 0; ms < 2; ms++)
                #pragma unroll
                for (int ns = 0; ns < 4; ns++) {
                    int colbase = wn * 16 + (ns & 1) * 8 + (ns >> 1) * 32 + t2;
                    int cw = colbase >> 1;
                    int rowb = row0 + wm * 32 + ms * 16 + g;
                    if (rowb < NN) {
                        __half2 h = __floats2half2_rn(acc[ms][ns][0], acc[ms][ns][1]);
                        g_xt_h[(size_t)rowb * 256 + kblk * 32 + cw] = h;
                    }
                    int rowb2 = rowb + 8;
                    if (rowb2 < NN) {
                        __half2 h = __floats2half2_rn(acc[ms][ns][2], acc[ms][ns][3]);
                        g_xt_h[(size_t)rowb2 * 256 + kblk * 32 + cw] = h;
                    }
                }
        } else {
            #pragma unroll
            for (int ms = 0; ms < 2; ms++)
                #pragma unroll
                for (int ns = 0; ns < 4; ns++)
                    #pragma unroll
                    for (int j = 0; j < 4; j++) {
                        int row = row0 + wm * 32 + ms * 16 + g + ((j >> 1) ? 8 : 0);
                        int c   = wn * 16 + (ns & 1) * 8 + (ns >> 1) * 32 + t2 + (j & 1);
                        if (row < NN) g_root[(size_t)row * 64 + c] = acc[ms][ns][j];
                    }
        }
    }
}

// ---------------- K_aggr: one warp per src node; v2 atomics -----------------
__global__ __launch_bounds__(256) void k_aggr()
{
    const int lane = threadIdx.x & 31;
    const int node = ((int)blockIdx.x * 256 + (int)threadIdx.x) >> 5;
    if (node >= NN) return;

    const int beg = g_off[node];
    const int end = g_off[node + 1];
    if (beg == end) return;

    const __half2* xr = g_xt_h + (size_t)node * 256;
    float2 f[8];
    #pragma unroll
    for (int k = 0; k < 8; k++) f[k] = __half22float2(xr[k * 32 + lane]);

    int e = beg;
    for (; e + 1 < end; e += 2) {
        int dstA = g_recdst[e];
        int dstB = g_recdst[e + 1];
        const float4* ga = (const float4*)&g_gk[(size_t)e * 8];
        float4 gA0 = ga[0], gA1 = ga[1], gB0 = ga[2], gB1 = ga[3];

        float accA0 = 0.f, accA1 = 0.f, accB0 = 0.f, accB1 = 0.f;
        float gAv[8] = {gA0.x, gA0.y, gA0.z, gA0.w, gA1.x, gA1.y, gA1.z, gA1.w};
        float gBv[8] = {gB0.x, gB0.y, gB0.z, gB0.w, gB1.x, gB1.y, gB1.z, gB1.w};
        #pragma unroll
        for (int k = 0; k < 8; k++) {
            accA0 = fmaf(gAv[k], f[k].x, accA0);
            accA1 = fmaf(gAv[k], f[k].y, accA1);
            accB0 = fmaf(gBv[k], f[k].x, accB0);
            accB1 = fmaf(gBv[k], f[k].y, accB1);
        }

        red_add_v2(&g_agg[(size_t)dstA * 64 + 2 * lane], accA0, accA1);
        red_add_v2(&g_agg[(size_t)dstB * 64 + 2 * lane], accB0, accB1);
    }
    if (e < end) {
        int dstA = g_recdst[e];
        const float4* ga = (const float4*)&g_gk[(size_t)e * 8];
        float4 gA0 = ga[0], gA1 = ga[1];
        float gAv[8] = {gA0.x, gA0.y, gA0.z, gA0.w, gA1.x, gA1.y, gA1.z, gA1.w};
        float accA0 = 0.f, accA1 = 0.f;
        #pragma unroll
        for (int k = 0; k < 8; k++) {
            accA0 = fmaf(gAv[k], f[k].x, accA0);
            accA1 = fmaf(gAv[k], f[k].y, accA1);
        }
        red_add_v2(&g_agg[(size_t)dstA * 64 + 2 * lane], accA0, accA1);
    }
}

// ---------------- K_combine ---------------------------------------------------
__global__ __launch_bounds__(256) void k_combine(
    const float* __restrict__ bias, float* __restrict__ out)
{
    const int c = threadIdx.x & 63;
    const int w = threadIdx.x >> 6;
    const float b = bias[c];

    float s = 0.0f, ss = 0.0f;
    for (int n = blockIdx.x * 4 + w; n < NN; n += gridDim.x * 4) {
        float cnt = (float)g_deg_dst[n];
        float inv = 1.0f / fmaxf(cnt, 1.0f);
        float v = g_agg[(size_t)n * 64 + c] * inv + g_root[(size_t)n * 64 + c] + b;
        out[(size_t)n * 64 + c] = v;
        s += v; ss += v * v;
    }

    __shared__ float shs[4][64];
    __shared__ float shq[4][64];
    shs[w][c] = s; shq[w][c] = ss;
    __syncthreads();
    if (threadIdx.x < 64) {
        float S  = shs[0][c] + shs[1][c] + shs[2][c] + shs[3][c];
        float SS = shq[0][c] + shq[1][c] + shq[2][c] + shq[3][c];
        atomicAdd(&g_sums[c], S);
        atomicAdd(&g_sums[64 + c], SS);
    }
}

// ---------------- K_norm (float4) ---------------------------------------------
__global__ __launch_bounds__(256) void k_norm(
    const float* __restrict__ gamma, const float* __restrict__ beta,
    float* __restrict__ out)
{
    long i = (long)blockIdx.x * blockDim.x + threadIdx.x;   // float4 index
    if (i >= (long)NN * 16) return;
    int c4 = (int)(i & 15) * 4;
    const float invN = 1.0f / (float)NN;
    float4 v = *(float4*)&out[i * 4];
    float r[4] = {v.x, v.y, v.z, v.w};
    #pragma unroll
    for (int j = 0; j < 4; j++) {
        int c = c4 + j;
        float mean = g_sums[c] * invN;
        float var  = g_sums[64 + c] * invN - mean * mean;
        float t = (r[j] - mean) * rsqrtf(var + 1e-5f) * gamma[c] + beta[c];
        r[j] = (t > 0.0f) ? t : 0.01f * t;
    }
    *(float4*)&out[i * 4] = make_float4(r[0], r[1], r[2], r[3]);
}

// ---------------- launcher ------------------------------------------------------
extern "C" void kernel_launch(void* const* d_in, const int* in_sizes, int n_in,
                              void* d_out, int out_size)
{
    const float* x      = (const float*)d_in[0];
    const void*  eidx   = d_in[1];
    const float* eattr  = (const float*)d_in[2];
    const float* Wg     = (const float*)d_in[3];
    const float* mu     = (const float*)d_in[4];
    const float* sigma  = (const float*)d_in[5];
    const float* Wr     = (const float*)d_in[6];
    const float* bias   = (const float*)d_in[7];
    const float* gamma  = (const float*)d_in[8];
    const float* beta   = (const float*)d_in[9];
    float* out = (float*)d_out;

    // one-time handles (created on the first, non-captured correctness call;
    // identical work on every call thereafter)
    static cudaStream_t s2 = nullptr;
    static cudaEvent_t ev_fork = nullptr, ev_join = nullptr;
    if (s2 == nullptr) {
        cudaStreamCreateWithFlags(&s2, cudaStreamNonBlocking);
        cudaEventCreateWithFlags(&ev_fork, cudaEventDisableTiming);
        cudaEventCreateWithFlags(&ev_join, cudaEventDisableTiming);
    }

    // fork stream B (matrix side: prepB -> gemm), independent of edge chain
    cudaEventRecord(ev_fork, 0);
    cudaStreamWaitEvent(s2, ev_fork, 0);
    k_prepB<<<144, 256, 0, s2>>>(Wg, Wr);
    k_gemm_tc<<<(NN + 127) / 128, 256, 0, s2>>>(x);
    cudaEventRecord(ev_join, s2);

    // chain A (edge side) on the default stream
    {
        long total = (long)NN * 64 + 2 * NN + 128;
        int blocks = (int)((total + 255) / 256);
        k_zero<<<blocks, 256>>>((const int*)eidx);
    }
    k_count<<<NBLK_CNT, 256>>>(eidx);
    k_scan_blk<<<NBLK_SCAN, 256>>>();
    k_scan_part<<<1, 256>>>();
    k_scan_add<<<NBLK_SCAN, 256>>>();
    k_scatter<<<(EE + 255) / 256, 256>>>(eidx, eattr, mu, sigma);

    // join: aggr needs scatter (A) + gemm (B)
    cudaStreamWaitEvent(0, ev_join, 0);
    k_aggr<<<(NN * 32 + 255) / 256, 256>>>();
    k_combine<<<512, 256>>>(bias, out);
    {
        int blocks = (int)(((long)NN * 16 + 255) / 256);
        k_norm<<<blocks, 256>>>(gamma, beta, out);
    }
}

// round 16
// speedup vs baseline: 1.2391x; 1.0187x over previous
#include <cuda_runtime.h>
#include <cuda_fp16.h>
#include <math.h>

#define NN 50000
#define EE 800000
#define KKER 8
#define NBLK_SCAN ((NN + 255) / 256)   // 196
#define NBLK_CNT  ((EE + 255) / 256)   // 3125

// ---------------- scratch (static device globals; no allocation) ------------
// xt layout: [row][kblk*32 + c'], half2 = channels (2c', 2c'+1)  = 51.2 MB
__device__ __half2 g_xt_h[(size_t)NN * 256];
__device__ float   g_root[(size_t)NN * 64];   // x @ W_root   12.8 MB
__device__ float   g_agg[(size_t)NN * 64];    // scatter target 12.8 MB
__device__ float   g_sums[128];               // [0:64) sum, [64:128) sumsq
__device__ int     g_is64;
__device__ __half  g_Bh[9 * 4096];            // pre-swizzled B tiles (73.7 KB)
// CSR-by-src structures
__device__ int     g_deg_src[NN];
__device__ int     g_deg_dst[NN];
__device__ int     g_off[NN + 1];
__device__ int     g_cur[NN];
__device__ int     g_part[NBLK_SCAN];
__device__ int     g_partoff[NBLK_SCAN];
__device__ int     g_recdst[EE];              // dst per CSR slot        3.2 MB
__device__ float   g_gk[(size_t)EE * 8];      // gauss weights, CSR order 25.6 MB

__device__ __forceinline__ unsigned h2_as_u32(__half2 h) {
    return *(unsigned*)&h;
}
__device__ __forceinline__ void red_add_v2(float* p, float a, float b) {
    asm volatile("red.global.add.v2.f32 [%0], {%1, %2};"
                 :: "l"(p), "f"(a), "f"(b) : "memory");
}

// ---------------- K_zero_small: deg arrays + sums + dtype sniff -------------
__global__ void k_zero_small(const int* __restrict__ eidx_raw) {
    long i = (long)blockIdx.x * blockDim.x + threadIdx.x;
    if (i < NN) g_deg_src[i] = 0;
    else if (i < 2 * NN) g_deg_dst[i - NN] = 0;
    else if (i < 2 * NN + 128) g_sums[i - 2 * NN] = 0.0f;

    if (blockIdx.x == 0) {
        __shared__ int sh[8];
        int acc = 0;
        for (int j = threadIdx.x; j < 2048; j += 256) acc |= eidx_raw[2 * j + 1];
        for (int o = 16; o > 0; o >>= 1) acc |= __shfl_xor_sync(0xffffffffu, acc, o);
        if ((threadIdx.x & 31) == 0) sh[threadIdx.x >> 5] = acc;
        __syncthreads();
        if (threadIdx.x == 0) {
            int a = 0;
            #pragma unroll
            for (int j = 0; j < 8; j++) a |= sh[j];
            g_is64 = (a == 0) ? 1 : 0;
        }
    }
}

// ---------------- K_zero_agg: g_agg only (float4), runs on stream B ---------
__global__ void k_zero_agg() {
    long i = (long)blockIdx.x * blockDim.x + threadIdx.x;
    if (i < (long)NN * 16)
        *(float4*)&g_agg[i * 4] = make_float4(0.f, 0.f, 0.f, 0.f);
}

// ---------------- K_count: src degree histogram only -------------------------
__global__ void k_count(const void* __restrict__ eidx) {
    int e = blockIdx.x * 256 + threadIdx.x;
    if (e >= EE) return;
    int src;
    if (g_is64) src = (int)((const long long*)eidx)[e];
    else        src = ((const int*)eidx)[e];
    atomicAdd(&g_deg_src[src], 1);
}

// ---------------- warp-shuffle scans ------------------------------------------
__global__ __launch_bounds__(256) void k_scan_blk() {
    __shared__ int wsum[8];
    const int t = threadIdx.x;
    const int i = blockIdx.x * 256 + t;
    const int lane = t & 31, w = t >> 5;
    int v = (i < NN) ? g_deg_src[i] : 0;
    int s = v;
    #pragma unroll
    for (int o = 1; o < 32; o <<= 1) {
        int n = __shfl_up_sync(0xffffffffu, s, o);
        if (lane >= o) s += n;
    }
    if (lane == 31) wsum[w] = s;
    __syncthreads();
    if (w == 0) {
        int ws = (lane < 8) ? wsum[lane] : 0;
        #pragma unroll
        for (int o = 1; o < 8; o <<= 1) {
            int n = __shfl_up_sync(0xffffffffu, ws, o);
            if (lane >= o) ws += n;
        }
        if (lane < 8) wsum[lane] = ws;
    }
    __syncthreads();
    int off = (w > 0) ? wsum[w - 1] : 0;
    if (i < NN) g_off[i] = off + s - v;       // exclusive
    if (t == 255) g_part[blockIdx.x] = wsum[7];
}

__global__ __launch_bounds__(256) void k_scan_part() {
    __shared__ int wsum[8];
    const int t = threadIdx.x;
    const int lane = t & 31, w = t >> 5;
    int v = (t < NBLK_SCAN) ? g_part[t] : 0;
    int s = v;
    #pragma unroll
    for (int o = 1; o < 32; o <<= 1) {
        int n = __shfl_up_sync(0xffffffffu, s, o);
        if (lane >= o) s += n;
    }
    if (lane == 31) wsum[w] = s;
    __syncthreads();
    if (w == 0) {
        int ws = (lane < 8) ? wsum[lane] : 0;
        #pragma unroll
        for (int o = 1; o < 8; o <<= 1) {
            int n = __shfl_up_sync(0xffffffffu, ws, o);
            if (lane >= o) ws += n;
        }
        if (lane < 8) wsum[lane] = ws;
    }
    __syncthreads();
    int off = (w > 0) ? wsum[w - 1] : 0;
    if (t < NBLK_SCAN) g_partoff[t] = off + s - v;
}

__global__ __launch_bounds__(256) void k_scan_add() {
    const int i = blockIdx.x * 256 + threadIdx.x;
    if (i < NN) {
        int o = g_off[i] + g_partoff[blockIdx.x];
        g_off[i] = o;
        g_cur[i] = o;
    }
    if (i == 0) g_off[NN] = EE;
}

// ---------------- K_scatter: bucket by src; gauss + dst histogram -----------
__global__ void k_scatter(const void* __restrict__ eidx,
                          const float* __restrict__ eattr,
                          const float* __restrict__ mu,
                          const float* __restrict__ sigma) {
    int e = blockIdx.x * 256 + threadIdx.x;
    if (e >= EE) return;
    int src, dst;
    if (g_is64) {
        const long long* e64 = (const long long*)eidx;
        src = (int)e64[e]; dst = (int)e64[EE + e];
    } else {
        const int* e32 = (const int*)eidx;
        src = e32[e]; dst = e32[EE + e];
    }
    float a0 = eattr[(size_t)e * 3 + 0];
    float a1 = eattr[(size_t)e * 3 + 1];
    float a2 = eattr[(size_t)e * 3 + 2];

    atomicAdd(&g_deg_dst[dst], 1);
    int pos = atomicAdd(&g_cur[src], 1);
    g_recdst[pos] = dst;

    float gk[8];
    #pragma unroll
    for (int k = 0; k < 8; k++) {
        float s0 = sigma[k * 3 + 0], s1 = sigma[k * 3 + 1], s2 = sigma[k * 3 + 2];
        float d0 = a0 - mu[k * 3 + 0];
        float d1 = a1 - mu[k * 3 + 1];
        float d2 = a2 - mu[k * 3 + 2];
        float iv0 = -0.5f / (1e-15f + s0 * s0);
        float iv1 = -0.5f / (1e-15f + s1 * s1);
        float iv2 = -0.5f / (1e-15f + s2 * s2);
        gk[k] = __expf(d0 * d0 * iv0 + d1 * d1 * iv1 + d2 * d2 * iv2);
    }
    float4* gdst = (float4*)&g_gk[(size_t)pos * 8];
    gdst[0] = make_float4(gk[0], gk[1], gk[2], gk[3]);
    gdst[1] = make_float4(gk[4], gk[5], gk[6], gk[7]);
}

// ---------------- K_prepB: B^T tiles -> fp16, XOR-swizzled ------------------
__global__ void k_prepB(const float* __restrict__ Wg, const float* __restrict__ Wr) {
    int idx = blockIdx.x * 256 + threadIdx.x;
    if (idx >= 9 * 4096) return;
    int kblk = idx >> 12;
    int n = (idx >> 6) & 63;
    int k = idx & 63;
    float v = (kblk < 8) ? Wg[k * 512 + kblk * 64 + n] : Wr[k * 64 + n];
    int swz = n * 64 + (((k >> 3) ^ (n & 7)) << 3) + (k & 7);
    g_Bh[kblk * 4096 + swz] = __float2half_rn(v);
}

// ---------------- tensor-core GEMM (single pass, 9-kblk loop) ----------------
__device__ __forceinline__ unsigned smem_u32(const void* p) {
    return (unsigned)__cvta_generic_to_shared(p);
}
__device__ __forceinline__ void mma16816(float d[4], const unsigned a[4],
                                         unsigned b0, unsigned b1) {
    asm volatile(
        "mma.sync.aligned.m16n8k16.row.col.f32.f16.f16.f32 "
        "{%0,%1,%2,%3}, {%4,%5,%6,%7}, {%8,%9}, {%0,%1,%2,%3};\n"
        : "+f"(d[0]), "+f"(d[1]), "+f"(d[2]), "+f"(d[3])
        : "r"(a[0]), "r"(a[1]), "r"(a[2]), "r"(a[3]), "r"(b0), "r"(b1));
}
#define LDSM_X4(r0, r1, r2, r3, addr)                                        \
    asm volatile("ldmatrix.sync.aligned.m8n8.x4.shared.b16 {%0,%1,%2,%3}, [%4];" \
                 : "=r"(r0), "=r"(r1), "=r"(r2), "=r"(r3) : "r"(addr))

__global__ __launch_bounds__(256) void k_gemm_tc(const float* __restrict__ x)
{
    __shared__ __half As[128 * 64];
    __shared__ __half Bs[64 * 64];

    const int row0 = blockIdx.x * 128;
    const int tid  = threadIdx.x;
    const int warp = tid >> 5;
    const int lane = tid & 31;
    const int g    = lane >> 2;
    const int t2   = (lane & 3) * 2;
    const int wm = warp & 3;
    const int wn = warp >> 2;

    #pragma unroll
    for (int j = 0; j < 4; j++) {
        int cid = tid + j * 256;
        int r = cid >> 3, kc = cid & 7;
        int gr = row0 + r;
        float4 v0 = make_float4(0.f, 0.f, 0.f, 0.f);
        float4 v1 = make_float4(0.f, 0.f, 0.f, 0.f);
        if (gr < NN) {
            v0 = *(const float4*)&x[(size_t)gr * 64 + kc * 8];
            v1 = *(const float4*)&x[(size_t)gr * 64 + kc * 8 + 4];
        }
        uint4 u;
        u.x = h2_as_u32(__floats2half2_rn(v0.x, v0.y));
        u.y = h2_as_u32(__floats2half2_rn(v0.z, v0.w));
        u.z = h2_as_u32(__floats2half2_rn(v1.x, v1.y));
        u.w = h2_as_u32(__floats2half2_rn(v1.z, v1.w));
        *(uint4*)&As[r * 64 + ((kc ^ (r & 7)) << 3)] = u;
    }
    __syncthreads();

    unsigned a[2][4][4];
    #pragma unroll
    for (int ms = 0; ms < 2; ms++)
        #pragma unroll
        for (int kk = 0; kk < 4; kk++) {
            int r  = wm * 32 + ms * 16 + (lane & 15);
            int ch = kk * 2 + (lane >> 4);
            unsigned ad = smem_u32(&As[r * 64 + ((ch ^ (r & 7)) << 3)]);
            LDSM_X4(a[ms][kk][0], a[ms][kk][1], a[ms][kk][2], a[ms][kk][3], ad);
        }

    const uint4* bsrc = (const uint4*)g_Bh;
    uint4* bdst = (uint4*)Bs;

    for (int kblk = 0; kblk < 9; kblk++) {
        __syncthreads();
        bdst[tid]       = bsrc[kblk * 512 + tid];
        bdst[tid + 256] = bsrc[kblk * 512 + tid + 256];
        __syncthreads();

        float acc[2][4][4];
        #pragma unroll
        for (int ms = 0; ms < 2; ms++)
            #pragma unroll
            for (int ns = 0; ns < 4; ns++)
                #pragma unroll
                for (int j = 0; j < 4; j++) acc[ms][ns][j] = 0.0f;

        #pragma unroll
        for (int kk = 0; kk < 4; kk++) {
            int ch = kk * 2 + (lane >> 4);
            int n0 = wn * 16 + (lane & 15);
            int n1 = n0 + 32;
            unsigned b0[4], b1[4];
            LDSM_X4(b0[0], b0[1], b0[2], b0[3],
                    smem_u32(&Bs[n0 * 64 + ((ch ^ (n0 & 7)) << 3)]));
            LDSM_X4(b1[0], b1[1], b1[2], b1[3],
                    smem_u32(&Bs[n1 * 64 + ((ch ^ (n1 & 7)) << 3)]));
            #pragma unroll
            for (int ms = 0; ms < 2; ms++) {
                mma16816(acc[ms][0], a[ms][kk], b0[0], b0[2]);
                mma16816(acc[ms][1], a[ms][kk], b0[1], b0[3]);
                mma16816(acc[ms][2], a[ms][kk], b1[0], b1[2]);
                mma16816(acc[ms][3], a[ms][kk], b1[1], b1[3]);
            }
        }

        if (kblk < 8) {
            // adjacent-channel pairing: h2 = (col, col+1); word c' = col/2
            #pragma unroll
            for (int ms = 0; ms < 2; ms++)
                #pragma unroll
                for (int ns = 0; ns < 4; ns++) {
                    int colbase = wn * 16 + (ns & 1) * 8 + (ns >> 1) * 32 + t2;
                    int cw = colbase >> 1;
                    int rowb = row0 + wm * 32 + ms * 16 + g;
                    if (rowb < NN) {
                        __half2 h = __floats2half2_rn(acc[ms][ns][0], acc[ms][ns][1]);
                        g_xt_h[(size_t)rowb * 256 + kblk * 32 + cw] = h;
                    }
                    int rowb2 = rowb + 8;
                    if (rowb2 < NN) {
                        __half2 h = __floats2half2_rn(acc[ms][ns][2], acc[ms][ns][3]);
                        g_xt_h[(size_t)rowb2 * 256 + kblk * 32 + cw] = h;
                    }
                }
        } else {
            #pragma unroll
            for (int ms = 0; ms < 2; ms++)
                #pragma unroll
                for (int ns = 0; ns < 4; ns++)
                    #pragma unroll
                    for (int j = 0; j < 4; j++) {
                        int row = row0 + wm * 32 + ms * 16 + g + ((j >> 1) ? 8 : 0);
                        int c   = wn * 16 + (ns & 1) * 8 + (ns >> 1) * 32 + t2 + (j & 1);
                        if (row < NN) g_root[(size_t)row * 64 + c] = acc[ms][ns][j];
                    }
        }
    }
}

// ---------------- K_aggr: one warp per src node; v2 atomics -----------------
__global__ __launch_bounds__(256) void k_aggr()
{
    const int lane = threadIdx.x & 31;
    const int node = ((int)blockIdx.x * 256 + (int)threadIdx.x) >> 5;
    if (node >= NN) return;

    const int beg = g_off[node];
    const int end = g_off[node + 1];
    if (beg == end) return;

    const __half2* xr = g_xt_h + (size_t)node * 256;
    float2 f[8];
    #pragma unroll
    for (int k = 0; k < 8; k++) f[k] = __half22float2(xr[k * 32 + lane]);

    int e = beg;
    for (; e + 1 < end; e += 2) {
        int dstA = g_recdst[e];
        int dstB = g_recdst[e + 1];
        const float4* ga = (const float4*)&g_gk[(size_t)e * 8];
        float4 gA0 = ga[0], gA1 = ga[1], gB0 = ga[2], gB1 = ga[3];

        float accA0 = 0.f, accA1 = 0.f, accB0 = 0.f, accB1 = 0.f;
        float gAv[8] = {gA0.x, gA0.y, gA0.z, gA0.w, gA1.x, gA1.y, gA1.z, gA1.w};
        float gBv[8] = {gB0.x, gB0.y, gB0.z, gB0.w, gB1.x, gB1.y, gB1.z, gB1.w};
        #pragma unroll
        for (int k = 0; k < 8; k++) {
            accA0 = fmaf(gAv[k], f[k].x, accA0);
            accA1 = fmaf(gAv[k], f[k].y, accA1);
            accB0 = fmaf(gBv[k], f[k].x, accB0);
            accB1 = fmaf(gBv[k], f[k].y, accB1);
        }

        red_add_v2(&g_agg[(size_t)dstA * 64 + 2 * lane], accA0, accA1);
        red_add_v2(&g_agg[(size_t)dstB * 64 + 2 * lane], accB0, accB1);
    }
    if (e < end) {
        int dstA = g_recdst[e];
        const float4* ga = (const float4*)&g_gk[(size_t)e * 8];
        float4 gA0 = ga[0], gA1 = ga[1];
        float gAv[8] = {gA0.x, gA0.y, gA0.z, gA0.w, gA1.x, gA1.y, gA1.z, gA1.w};
        float accA0 = 0.f, accA1 = 0.f;
        #pragma unroll
        for (int k = 0; k < 8; k++) {
            accA0 = fmaf(gAv[k], f[k].x, accA0);
            accA1 = fmaf(gAv[k], f[k].y, accA1);
        }
        red_add_v2(&g_agg[(size_t)dstA * 64 + 2 * lane], accA0, accA1);
    }
}

// ---------------- K_combine ---------------------------------------------------
__global__ __launch_bounds__(256) void k_combine(
    const float* __restrict__ bias, float* __restrict__ out)
{
    const int c = threadIdx.x & 63;
    const int w = threadIdx.x >> 6;
    const float b = bias[c];

    float s = 0.0f, ss = 0.0f;
    for (int n = blockIdx.x * 4 + w; n < NN; n += gridDim.x * 4) {
        float cnt = (float)g_deg_dst[n];
        float inv = 1.0f / fmaxf(cnt, 1.0f);
        float v = g_agg[(size_t)n * 64 + c] * inv + g_root[(size_t)n * 64 + c] + b;
        out[(size_t)n * 64 + c] = v;
        s += v; ss += v * v;
    }

    __shared__ float shs[4][64];
    __shared__ float shq[4][64];
    shs[w][c] = s; shq[w][c] = ss;
    __syncthreads();
    if (threadIdx.x < 64) {
        float S  = shs[0][c] + shs[1][c] + shs[2][c] + shs[3][c];
        float SS = shq[0][c] + shq[1][c] + shq[2][c] + shq[3][c];
        atomicAdd(&g_sums[c], S);
        atomicAdd(&g_sums[64 + c], SS);
    }
}

// ---------------- K_norm (float4) ---------------------------------------------
__global__ __launch_bounds__(256) void k_norm(
    const float* __restrict__ gamma, const float* __restrict__ beta,
    float* __restrict__ out)
{
    long i = (long)blockIdx.x * blockDim.x + threadIdx.x;   // float4 index
    if (i >= (long)NN * 16) return;
    int c4 = (int)(i & 15) * 4;
    const float invN = 1.0f / (float)NN;
    float4 v = *(float4*)&out[i * 4];
    float r[4] = {v.x, v.y, v.z, v.w};
    #pragma unroll
    for (int j = 0; j < 4; j++) {
        int c = c4 + j;
        float mean = g_sums[c] * invN;
        float var  = g_sums[64 + c] * invN - mean * mean;
        float t = (r[j] - mean) * rsqrtf(var + 1e-5f) * gamma[c] + beta[c];
        r[j] = (t > 0.0f) ? t : 0.01f * t;
    }
    *(float4*)&out[i * 4] = make_float4(r[0], r[1], r[2], r[3]);
}

// ---------------- launcher ------------------------------------------------------
extern "C" void kernel_launch(void* const* d_in, const int* in_sizes, int n_in,
                              void* d_out, int out_size)
{
    const float* x      = (const float*)d_in[0];
    const void*  eidx   = d_in[1];
    const float* eattr  = (const float*)d_in[2];
    const float* Wg     = (const float*)d_in[3];
    const float* mu     = (const float*)d_in[4];
    const float* sigma  = (const float*)d_in[5];
    const float* Wr     = (const float*)d_in[6];
    const float* bias   = (const float*)d_in[7];
    const float* gamma  = (const float*)d_in[8];
    const float* beta   = (const float*)d_in[9];
    float* out = (float*)d_out;

    static cudaStream_t s2 = nullptr;
    static cudaEvent_t ev_fork = nullptr, ev_join = nullptr;
    if (s2 == nullptr) {
        cudaStreamCreateWithFlags(&s2, cudaStreamNonBlocking);
        cudaEventCreateWithFlags(&ev_fork, cudaEventDisableTiming);
        cudaEventCreateWithFlags(&ev_join, cudaEventDisableTiming);
    }

    // fork stream B: zero_agg -> prepB -> gemm (independent of edge chain)
    cudaEventRecord(ev_fork, 0);
    cudaStreamWaitEvent(s2, ev_fork, 0);
    k_zero_agg<<<(int)(((long)NN * 16 + 255) / 256), 256, 0, s2>>>();
    k_prepB<<<144, 256, 0, s2>>>(Wg, Wr);
    k_gemm_tc<<<(NN + 127) / 128, 256, 0, s2>>>(x);
    cudaEventRecord(ev_join, s2);

    // chain A (edge side) on the default stream
    k_zero_small<<<(2 * NN + 128 + 255) / 256, 256>>>((const int*)eidx);
    k_count<<<NBLK_CNT, 256>>>(eidx);
    k_scan_blk<<<NBLK_SCAN, 256>>>();
    k_scan_part<<<1, 256>>>();
    k_scan_add<<<NBLK_SCAN, 256>>>();
    k_scatter<<<(EE + 255) / 256, 256>>>(eidx, eattr, mu, sigma);

    // join: aggr needs scatter (A) + gemm/zero_agg (B)
    cudaStreamWaitEvent(0, ev_join, 0);
    k_aggr<<<(NN * 32 + 255) / 256, 256>>>();
    k_combine<<<512, 256>>>(bias, out);
    {
        int blocks = (int)(((long)NN * 16 + 255) / 256);
        k_norm<<<blocks, 256>>>(gamma, beta, out);
    }
}